// round 9
// baseline (speedup 1.0000x reference)
#include <cuda_runtime.h>
#include <cuda_bf16.h>
#include <math.h>
#include <stdint.h>

#define Bq 128
#define Sq 4096
#define Hq 512
#define Vq 32000
#define NCHUNK 64

// ---------------- scratch (no allocations allowed) ----------------
__device__ float g_hnew[Bq * Hq];
__device__ float g_scores[Bq * Sq];
__device__ float g_pm[Bq * NCHUNK];
__device__ float g_pz[Bq * NCHUNK];
__device__ float g_pctx[Bq * NCHUNK * Hq];
__device__ float g_concat_in[Bq * 2 * Hq];
__device__ float g_concat_out[Bq * Hq];
__device__ float g_gemm_part [8 * Bq * 3 * Hq];
__device__ float g_gemm_part2[8 * Bq * 3 * Hq];

// ---------------- tf32 tensor-core GEMM, 3-deep cp.async ring ----------------
__device__ __forceinline__ uint32_t f2tf32(float x) {
    uint32_t r;
    asm("cvt.rna.tf32.f32 %0, %1;" : "=r"(r) : "f"(x));
    return r;
}
__device__ __forceinline__ void mma_tf32(float* d, const uint32_t* a, const uint32_t* b) {
    asm("mma.sync.aligned.m16n8k8.row.col.f32.tf32.tf32.f32 "
        "{%0,%1,%2,%3}, {%4,%5,%6,%7}, {%8,%9}, {%0,%1,%2,%3};"
        : "+f"(d[0]), "+f"(d[1]), "+f"(d[2]), "+f"(d[3])
        : "r"(a[0]), "r"(a[1]), "r"(a[2]), "r"(a[3]), "r"(b[0]), "r"(b[1]));
}
__device__ __forceinline__ void cp16(void* dst_smem, const void* src) {
    uint32_t d = (uint32_t)__cvta_generic_to_shared(dst_smem);
    asm volatile("cp.async.ca.shared.global [%0], [%1], 16;" :: "r"(d), "l"(src));
}
__device__ __forceinline__ void cp_commit() { asm volatile("cp.async.commit_group;"); }
template<int N> __device__ __forceinline__ void cp_wait() {
    asm volatile("cp.async.wait_group %0;" :: "n"(N));
}

#define LDA 20
#define TILE_F (128 * LDA)
#define GEMM_SMEM_BYTES (3 * 2 * TILE_F * 4)

// C[128,N](cols nblk..nblk+127) += sum over nsteps k-tiles of 16.
// aptr0/aptr1: global sources for A rows r0, r0+64 at this thread's k4 offset.
// wptr0/wptr1: same for W rows nblk+r0, nblk+r0+64. All advance +16 floats/step.
// prec: 3 -> tf32x3 (fp32-grade), 2 -> tf32x2 (~2e-4)
__device__ __forceinline__
void gemm_body(const float* aptr0, const float* aptr1,
               const float* wptr0, const float* wptr1,
               const float* __restrict__ bias,
               float* __restrict__ C, int N,
               float* __restrict__ part,
               int nblk, int nsteps, int prec)
{
    extern __shared__ float smx[];
    float* Asm = smx;
    float* Wsm = smx + 3 * TILE_F;

    int t = threadIdx.x;
    int wid = t >> 5, lane = t & 31;
    int lr = lane >> 2, lc = lane & 3;
    int m0 = (wid & 3) * 32;
    int n0 = (wid >> 2) * 64;
    int r0 = t >> 2;
    int k4 = (t & 3) * 4;

    float acc[2][8][4];
#pragma unroll
    for (int i = 0; i < 2; i++)
#pragma unroll
        for (int j = 0; j < 8; j++)
#pragma unroll
            for (int c = 0; c < 4; c++) acc[i][j][c] = 0.f;

#define STAGE(buf, step)                                              \
    do {                                                              \
        float* Ad = Asm + (buf) * TILE_F;                             \
        float* Wd = Wsm + (buf) * TILE_F;                             \
        cp16(Ad + r0 * LDA + k4,        aptr0 + (step) * 16);         \
        cp16(Ad + (r0 + 64) * LDA + k4, aptr1 + (step) * 16);         \
        cp16(Wd + r0 * LDA + k4,        wptr0 + (step) * 16);         \
        cp16(Wd + (r0 + 64) * LDA + k4, wptr1 + (step) * 16);         \
        cp_commit();                                                  \
    } while (0)

#pragma unroll
    for (int p = 0; p < 3; p++) {
        if (p < nsteps) STAGE(p, p);
        else cp_commit();
    }

    for (int i = 0; i < nsteps; i++) {
        cp_wait<2>();
        __syncthreads();
        int buf = i % 3;
        const float* Ab = Asm + buf * TILE_F;
        const float* Wb = Wsm + buf * TILE_F;
#pragma unroll
        for (int ks = 0; ks < 2; ks++) {
            int k0 = ks * 8;
            uint32_t ah[2][4], al[2][4];
#pragma unroll
            for (int tt = 0; tt < 2; tt++) {
                int rb = m0 + tt * 16;
#pragma unroll
                for (int q = 0; q < 4; q++) {
                    int rr = rb + lr + (q & 1) * 8;
                    int cc = k0 + lc + (q >> 1) * 4;
                    float x = Ab[rr * LDA + cc];
                    uint32_t hi = f2tf32(x);
                    ah[tt][q] = hi;
                    if (prec == 3) al[tt][q] = f2tf32(x - __uint_as_float(hi));
                }
            }
#pragma unroll
            for (int j = 0; j < 8; j++) {
                int rn = (n0 + j * 8 + lr) * LDA;
                float x0 = Wb[rn + k0 + lc];
                float x1 = Wb[rn + k0 + lc + 4];
                uint32_t bh[2], bl[2];
                bh[0] = f2tf32(x0); bl[0] = f2tf32(x0 - __uint_as_float(bh[0]));
                bh[1] = f2tf32(x1); bl[1] = f2tf32(x1 - __uint_as_float(bh[1]));
#pragma unroll
                for (int tt = 0; tt < 2; tt++) {
                    mma_tf32(acc[tt][j], ah[tt], bh);
                    mma_tf32(acc[tt][j], ah[tt], bl);
                    if (prec == 3) mma_tf32(acc[tt][j], al[tt], bh);
                }
            }
        }
        __syncthreads();
        int nx = i + 3;
        if (nx < nsteps) STAGE(buf, nx);
        else cp_commit();
    }
#undef STAGE

    if (part) {
#pragma unroll
        for (int tt = 0; tt < 2; tt++)
#pragma unroll
            for (int j = 0; j < 8; j++) {
                int gr = m0 + tt * 16 + lr;
                int gc = nblk + n0 + j * 8 + 2 * lc;
                *(float2*)(part + (size_t)gr * N + gc) = make_float2(acc[tt][j][0], acc[tt][j][1]);
                *(float2*)(part + (size_t)(gr + 8) * N + gc) = make_float2(acc[tt][j][2], acc[tt][j][3]);
            }
    } else {
#pragma unroll
        for (int tt = 0; tt < 2; tt++)
#pragma unroll
            for (int j = 0; j < 8; j++) {
                int gr = m0 + tt * 16 + lr;
                int gc = nblk + n0 + j * 8 + 2 * lc;
                float b0 = bias ? bias[gc] : 0.f;
                float b1 = bias ? bias[gc + 1] : 0.f;
                *(float2*)(C + (size_t)gr * N + gc) = make_float2(acc[tt][j][0] + b0, acc[tt][j][1] + b1);
                *(float2*)(C + (size_t)(gr + 8) * N + gc) = make_float2(acc[tt][j][2] + b0, acc[tt][j][3] + b1);
            }
    }
}

// generic GEMM: C[128,N] = A[128,K] @ W[N,K]^T, grid (N/128, ksplit)
__global__ __launch_bounds__(256, 2)
void gemm_tf32(const float* __restrict__ A, int K,
               const float* __restrict__ W,
               const float* __restrict__ bias,
               float* __restrict__ C, int N,
               float* __restrict__ Cpart, int prec)
{
    int ksplit = gridDim.y;
    int klen = K / ksplit;
    int kstart = blockIdx.y * klen;
    int nblk = blockIdx.x * 128;
    int t = threadIdx.x;
    int r0 = t >> 2;
    int k4 = (t & 3) * 4;
    float* part = (ksplit > 1) ? (Cpart + (size_t)blockIdx.y * 128 * N) : nullptr;
    gemm_body(A + (size_t)r0 * K + kstart + k4,
              A + (size_t)(r0 + 64) * K + kstart + k4,
              W + (size_t)(nblk + r0) * K + kstart + k4,
              W + (size_t)(nblk + r0 + 64) * K + kstart + k4,
              bias, C, N, part, nblk, klen / 16, prec);
}

// fused GRU GEMMs + embedding gather: grid (12, 8, 2)
// z=0: gx = gathered-embeddings[128, 2048] @ W_ih^T  (A staged straight from tables)
// z=1: gh = h[128, 512] @ W_hh^T
__global__ __launch_bounds__(256, 2)
void gemm_gru(const float* __restrict__ hprev,
              const float* __restrict__ W_ih, const float* __restrict__ W_hh,
              const int* __restrict__ seq, const int* __restrict__ pos,
              const int* __restrict__ yr, const int* __restrict__ fr,
              const float* __restrict__ et, const float* __restrict__ ep,
              const float* __restrict__ ey, const float* __restrict__ ei)
{
    int N = 3 * Hq;
    int nblk = blockIdx.x * 128;
    int t = threadIdx.x;
    int r0 = t >> 2;
    int k4 = (t & 3) * 4;
    if (blockIdx.z == 0) {
        int K = 4 * Hq;                 // 2048
        int klen = K / 8;               // 256 -> one table per split
        int kstart = blockIdx.y * klen;
        int region = blockIdx.y >> 1;   // 0:tok 1:pos 2:year 3:inst
        int coff = (blockIdx.y & 1) * 256 + k4;
        const float* tbl; const int* idxa;
        if (region == 0)      { tbl = et; idxa = seq; }
        else if (region == 1) { tbl = ep; idxa = pos; }
        else if (region == 2) { tbl = ey; idxa = yr; }
        else                  { tbl = ei; idxa = fr; }
        const float* a0 = tbl + (size_t)idxa[r0] * Hq + coff;
        const float* a1 = tbl + (size_t)idxa[r0 + 64] * Hq + coff;
        gemm_body(a0, a1,
                  W_ih + (size_t)(nblk + r0) * K + kstart + k4,
                  W_ih + (size_t)(nblk + r0 + 64) * K + kstart + k4,
                  nullptr, nullptr, N,
                  g_gemm_part + (size_t)blockIdx.y * 128 * N,
                  nblk, klen / 16, 3);
    } else {
        int K = Hq;
        int klen = K / 8;               // 64
        int kstart = blockIdx.y * klen;
        gemm_body(hprev + (size_t)r0 * K + kstart + k4,
                  hprev + (size_t)(r0 + 64) * K + kstart + k4,
                  W_hh + (size_t)(nblk + r0) * K + kstart + k4,
                  W_hh + (size_t)(nblk + r0 + 64) * K + kstart + k4,
                  nullptr, nullptr, N,
                  g_gemm_part2 + (size_t)blockIdx.y * 128 * N,
                  nblk, klen / 16, 3);
    }
}

__global__ void reduce_split(const float* __restrict__ part, const float* __restrict__ bias,
                             float* __restrict__ C, int total, int N, int ksplit, int act)
{
    int idx = blockIdx.x * 256 + threadIdx.x;
    if (idx >= total) return;
    float s = 0.f;
    for (int z = 0; z < ksplit; z++) s += part[(size_t)z * total + idx];
    s += bias[idx % N];
    if (act == 1) s = tanhf(s);
    C[idx] = s;
}

// ---------------- fused split-K reduce + GRU gates ----------------
__global__ void gate_fused_kernel(const float* __restrict__ hprev,
                                  const float* __restrict__ b_ih,
                                  const float* __restrict__ b_hh,
                                  float* __restrict__ out_h)
{
    int idx = blockIdx.x * 256 + threadIdx.x;
    int b = idx >> 9;
    int j = idx & 511;
    float xr = 0.f, xz = 0.f, xn = 0.f, hr = 0.f, hz = 0.f, hn = 0.f;
#pragma unroll
    for (int z = 0; z < 8; z++) {
        const float* P0 = g_gemm_part  + ((size_t)z * Bq + b) * (3 * Hq);
        const float* P1 = g_gemm_part2 + ((size_t)z * Bq + b) * (3 * Hq);
        xr += P0[j]; xz += P0[Hq + j]; xn += P0[2 * Hq + j];
        hr += P1[j]; hz += P1[Hq + j]; hn += P1[2 * Hq + j];
    }
    xr += b_ih[j]; xz += b_ih[Hq + j]; xn += b_ih[2 * Hq + j];
    hr += b_hh[j]; hz += b_hh[Hq + j]; hn += b_hh[2 * Hq + j];
    float r = 1.f / (1.f + __expf(-(xr + hr)));
    float z = 1.f / (1.f + __expf(-(xz + hz)));
    float n = tanhf(xn + r * hn);
    float hnew = (1.f - z) * n + z * hprev[idx];
    g_hnew[idx] = hnew;
    g_concat_in[(size_t)b * 2 * Hq + j] = hnew;
    if (out_h) out_h[idx] = hnew;
}

// ---------------- fused attention: single pass over enc ----------------
__global__ __launch_bounds__(128)
void attn_fused_kernel(const float* __restrict__ enc)
{
    int b = blockIdx.y;
    int t = threadIdx.x;
    int w = t >> 5;
    int lane = t & 31;
    int chunk = blockIdx.x * 4 + w;

    const float4* h4 = (const float4*)(g_hnew + (size_t)b * Hq);
    float4 h0 = h4[lane];
    float4 h1 = h4[lane + 32];
    float4 h2 = h4[lane + 64];
    float4 h3 = h4[lane + 96];

    float m = -1e30f, Z = 0.f;
    float4 c0 = make_float4(0.f,0.f,0.f,0.f), c1 = c0, c2 = c0, c3 = c0;

    int sbase = chunk * 64;
#pragma unroll 2
    for (int s0 = 0; s0 < 64; s0++) {
        int s = sbase + s0;
        const float4* e4 = (const float4*)(enc + ((size_t)s * Bq + b) * Hq);
        float4 e0 = e4[lane];
        float4 e1 = e4[lane + 32];
        float4 e2 = e4[lane + 64];
        float4 e3 = e4[lane + 96];
        float dp = e0.x*h0.x + e0.y*h0.y + e0.z*h0.z + e0.w*h0.w
                 + e1.x*h1.x + e1.y*h1.y + e1.z*h1.z + e1.w*h1.w
                 + e2.x*h2.x + e2.y*h2.y + e2.z*h2.z + e2.w*h2.w
                 + e3.x*h3.x + e3.y*h3.y + e3.z*h3.z + e3.w*h3.w;
#pragma unroll
        for (int off = 16; off > 0; off >>= 1)
            dp += __shfl_xor_sync(0xffffffffu, dp, off);
        if (lane == 0) g_scores[(size_t)b * Sq + s] = dp;
        if (dp <= m) {
            float p = __expf(dp - m);
            Z += p;
            c0.x += p*e0.x; c0.y += p*e0.y; c0.z += p*e0.z; c0.w += p*e0.w;
            c1.x += p*e1.x; c1.y += p*e1.y; c1.z += p*e1.z; c1.w += p*e1.w;
            c2.x += p*e2.x; c2.y += p*e2.y; c2.z += p*e2.z; c2.w += p*e2.w;
            c3.x += p*e3.x; c3.y += p*e3.y; c3.z += p*e3.z; c3.w += p*e3.w;
        } else {
            float corr = __expf(m - dp);
            Z = Z * corr + 1.f;
            c0.x = c0.x*corr + e0.x; c0.y = c0.y*corr + e0.y; c0.z = c0.z*corr + e0.z; c0.w = c0.w*corr + e0.w;
            c1.x = c1.x*corr + e1.x; c1.y = c1.y*corr + e1.y; c1.z = c1.z*corr + e1.z; c1.w = c1.w*corr + e1.w;
            c2.x = c2.x*corr + e2.x; c2.y = c2.y*corr + e2.y; c2.z = c2.z*corr + e2.z; c2.w = c2.w*corr + e2.w;
            c3.x = c3.x*corr + e3.x; c3.y = c3.y*corr + e3.y; c3.z = c3.z*corr + e3.z; c3.w = c3.w*corr + e3.w;
            m = dp;
        }
    }

    int pc = b * NCHUNK + chunk;
    float4* pctx = (float4*)(g_pctx + (size_t)pc * Hq);
    pctx[lane]      = c0;
    pctx[lane + 32] = c1;
    pctx[lane + 64] = c2;
    pctx[lane + 96] = c3;
    if (lane == 0) { g_pm[pc] = m; g_pz[pc] = Z; }
}

// ---------------- combine partials -> context + write attn weights ----------------
__global__ __launch_bounds__(128)
void attn_reduce_kernel(float* __restrict__ out_attn)
{
    __shared__ float scale[NCHUNK];
    __shared__ float smax[NCHUNK];
    __shared__ float ssum[NCHUNK];
    __shared__ float sM, sZinv;
    int b = blockIdx.x;
    int t = threadIdx.x;
    if (t < NCHUNK) { smax[t] = g_pm[b * NCHUNK + t]; ssum[t] = g_pz[b * NCHUNK + t]; }
    __syncthreads();
    if (t == 0) {
        float M = -1e30f;
        for (int c = 0; c < NCHUNK; c++) M = fmaxf(M, smax[c]);
        float Zt = 0.f;
        for (int c = 0; c < NCHUNK; c++) {
            float sc = __expf(smax[c] - M);
            scale[c] = sc;
            Zt += ssum[c] * sc;
        }
        sM = M;
        sZinv = 1.f / Zt;
    }
    __syncthreads();
    float zinv = sZinv;
    float M = sM;
    float a0 = 0.f, a1 = 0.f, a2 = 0.f, a3 = 0.f;
    for (int c = 0; c < NCHUNK; c++) {
        const float4 v = *(const float4*)(g_pctx + ((size_t)(b * NCHUNK + c)) * Hq + t * 4);
        float sc = scale[c];
        a0 += v.x * sc; a1 += v.y * sc; a2 += v.z * sc; a3 += v.w * sc;
    }
    float4 r = make_float4(a0 * zinv, a1 * zinv, a2 * zinv, a3 * zinv);
    *(float4*)(g_concat_in + (size_t)b * 2 * Hq + Hq + t * 4) = r;

    if (out_attn) {
        const float* sc_row = g_scores + (size_t)b * Sq;
        float* out_row = out_attn + (size_t)b * Sq;
        for (int i = t; i < Sq; i += 128)
            out_row[i] = __expf(sc_row[i] - M) * zinv;
    }
}

// ---------------- launch ----------------
extern "C" void kernel_launch(void* const* d_in, const int* in_sizes, int n_in,
                              void* d_out, int out_size)
{
    const int* input_seq   = (const int*)d_in[0];
    const int* positions   = (const int*)d_in[1];
    const int* years       = (const int*)d_in[2];
    const int* froms       = (const int*)d_in[3];
    const float* last_h    = (const float*)d_in[4];
    const float* enc       = (const float*)d_in[5];
    const float* emb_tok   = (const float*)d_in[6];
    const float* emb_pos   = (const float*)d_in[7];
    const float* emb_year  = (const float*)d_in[8];
    const float* emb_inst  = (const float*)d_in[9];
    const float* W_ih      = (const float*)d_in[10];
    const float* b_ih      = (const float*)d_in[11];
    const float* W_hh      = (const float*)d_in[12];
    const float* b_hh      = (const float*)d_in[13];
    const float* W_concat  = (const float*)d_in[14];
    const float* b_concat  = (const float*)d_in[15];
    const float* W_out     = (const float*)d_in[16];
    const float* b_out     = (const float*)d_in[17];

    float* out = (float*)d_out;
    float* out_logits = out;
    float* out_h = nullptr;
    float* out_attn = nullptr;
    long long need = (long long)Bq * Vq + (long long)Bq * Hq + (long long)Bq * Sq;
    if ((long long)out_size >= need) {
        out_h = out + (size_t)Bq * Vq;
        out_attn = out_h + (size_t)Bq * Hq;
    }

    float *part, *concat_in, *concat_out;
    cudaGetSymbolAddress((void**)&part, g_gemm_part);
    cudaGetSymbolAddress((void**)&concat_in, g_concat_in);
    cudaGetSymbolAddress((void**)&concat_out, g_concat_out);

    cudaFuncSetAttribute(gemm_tf32, cudaFuncAttributeMaxDynamicSharedMemorySize, GEMM_SMEM_BYTES);
    cudaFuncSetAttribute(gemm_gru, cudaFuncAttributeMaxDynamicSharedMemorySize, GEMM_SMEM_BYTES);

    // 1. gx (embedding gather fused) AND gh in one launch (split-K 8, tf32x3)
    gemm_gru<<<dim3(12, 8, 2), 256, GEMM_SMEM_BYTES>>>(last_h, W_ih, W_hh,
        input_seq, positions, years, froms, emb_tok, emb_pos, emb_year, emb_inst);
    // 2. fused split-K reduce + gates -> h_new
    gate_fused_kernel<<<(Bq * Hq) / 256, 256>>>(last_h, b_ih, b_hh, out_h);
    // 3. fused scores + online-softmax context (single pass over enc)
    attn_fused_kernel<<<dim3(16, Bq), 128>>>(enc);
    // 4. combine partials -> context + attn weights output
    attn_reduce_kernel<<<Bq, 128>>>(out_attn);
    // 5. concat_out = tanh(concat_in @ W_concat^T + b_concat) (tf32x3, split-K 8)
    gemm_tf32<<<dim3(4, 8), 256, GEMM_SMEM_BYTES>>>(concat_in, 2 * Hq, W_concat, nullptr, nullptr, Hq, part, 3);
    reduce_split<<<(Bq * Hq + 255) / 256, 256>>>(part, b_concat, concat_out, Bq * Hq, Hq, 8, 1);
    // 6. logits = concat_out @ W_out^T + b_out  (tf32x2, split-K 1, direct out)
    gemm_tf32<<<dim3(Vq / 128, 1), 256, GEMM_SMEM_BYTES>>>(concat_out, Hq, W_out, b_out, out_logits, Vq, nullptr, 2);
}

// round 10
// speedup vs baseline: 1.0572x; 1.0572x over previous
#include <cuda_runtime.h>
#include <cuda_bf16.h>
#include <math.h>
#include <stdint.h>

#define Bq 128
#define Sq 4096
#define Hq 512
#define Vq 32000
#define NCHUNK 32           // 32 chunks of 128 s each

// ---------------- scratch (no allocations allowed) ----------------
__device__ float g_hnew[Bq * Hq];
__device__ float g_scores[Bq * Sq];
__device__ float g_pm[Bq * NCHUNK];
__device__ float g_pz[Bq * NCHUNK];
__device__ float g_scale[Bq * NCHUNK];     // exp(m_c - M)/Z per chunk
__device__ float g_pctx[Bq * NCHUNK * Hq];
__device__ float g_M[Bq];
__device__ float g_Zinv[Bq];
__device__ float g_concat_in[Bq * 2 * Hq];
__device__ float g_concat_out[Bq * Hq];
__device__ float g_gemm_part [8 * Bq * 3 * Hq];
__device__ float g_gemm_part2[8 * Bq * 3 * Hq];

// ---------------- tf32 tensor-core GEMM, 3-deep cp.async ring ----------------
__device__ __forceinline__ uint32_t f2tf32(float x) {
    uint32_t r;
    asm("cvt.rna.tf32.f32 %0, %1;" : "=r"(r) : "f"(x));
    return r;
}
__device__ __forceinline__ void mma_tf32(float* d, const uint32_t* a, const uint32_t* b) {
    asm("mma.sync.aligned.m16n8k8.row.col.f32.tf32.tf32.f32 "
        "{%0,%1,%2,%3}, {%4,%5,%6,%7}, {%8,%9}, {%0,%1,%2,%3};"
        : "+f"(d[0]), "+f"(d[1]), "+f"(d[2]), "+f"(d[3])
        : "r"(a[0]), "r"(a[1]), "r"(a[2]), "r"(a[3]), "r"(b[0]), "r"(b[1]));
}
__device__ __forceinline__ void cp16(void* dst_smem, const void* src) {
    uint32_t d = (uint32_t)__cvta_generic_to_shared(dst_smem);
    asm volatile("cp.async.ca.shared.global [%0], [%1], 16;" :: "r"(d), "l"(src));
}
__device__ __forceinline__ void cp_commit() { asm volatile("cp.async.commit_group;"); }
template<int N> __device__ __forceinline__ void cp_wait() {
    asm volatile("cp.async.wait_group %0;" :: "n"(N));
}

#define LDA 20
#define TILE_F (128 * LDA)
#define GEMM_SMEM_BYTES (3 * 2 * TILE_F * 4)

__device__ __forceinline__
void gemm_body(const float* aptr0, const float* aptr1,
               const float* wptr0, const float* wptr1,
               const float* __restrict__ bias,
               float* __restrict__ C, int N,
               float* __restrict__ part,
               int nblk, int nsteps, int prec)
{
    extern __shared__ float smx[];
    float* Asm = smx;
    float* Wsm = smx + 3 * TILE_F;

    int t = threadIdx.x;
    int wid = t >> 5, lane = t & 31;
    int lr = lane >> 2, lc = lane & 3;
    int m0 = (wid & 3) * 32;
    int n0 = (wid >> 2) * 64;
    int r0 = t >> 2;
    int k4 = (t & 3) * 4;

    float acc[2][8][4];
#pragma unroll
    for (int i = 0; i < 2; i++)
#pragma unroll
        for (int j = 0; j < 8; j++)
#pragma unroll
            for (int c = 0; c < 4; c++) acc[i][j][c] = 0.f;

#define STAGE(buf, step)                                              \
    do {                                                              \
        float* Ad = Asm + (buf) * TILE_F;                             \
        float* Wd = Wsm + (buf) * TILE_F;                             \
        cp16(Ad + r0 * LDA + k4,        aptr0 + (step) * 16);         \
        cp16(Ad + (r0 + 64) * LDA + k4, aptr1 + (step) * 16);         \
        cp16(Wd + r0 * LDA + k4,        wptr0 + (step) * 16);         \
        cp16(Wd + (r0 + 64) * LDA + k4, wptr1 + (step) * 16);         \
        cp_commit();                                                  \
    } while (0)

#pragma unroll
    for (int p = 0; p < 3; p++) {
        if (p < nsteps) STAGE(p, p);
        else cp_commit();
    }

    for (int i = 0; i < nsteps; i++) {
        cp_wait<2>();
        __syncthreads();
        int buf = i % 3;
        const float* Ab = Asm + buf * TILE_F;
        const float* Wb = Wsm + buf * TILE_F;
#pragma unroll
        for (int ks = 0; ks < 2; ks++) {
            int k0 = ks * 8;
            uint32_t ah[2][4], al[2][4];
#pragma unroll
            for (int tt = 0; tt < 2; tt++) {
                int rb = m0 + tt * 16;
#pragma unroll
                for (int q = 0; q < 4; q++) {
                    int rr = rb + lr + (q & 1) * 8;
                    int cc = k0 + lc + (q >> 1) * 4;
                    float x = Ab[rr * LDA + cc];
                    uint32_t hi = f2tf32(x);
                    ah[tt][q] = hi;
                    if (prec == 3) al[tt][q] = f2tf32(x - __uint_as_float(hi));
                }
            }
#pragma unroll
            for (int j = 0; j < 8; j++) {
                int rn = (n0 + j * 8 + lr) * LDA;
                float x0 = Wb[rn + k0 + lc];
                float x1 = Wb[rn + k0 + lc + 4];
                uint32_t bh[2], bl[2];
                bh[0] = f2tf32(x0); bl[0] = f2tf32(x0 - __uint_as_float(bh[0]));
                bh[1] = f2tf32(x1); bl[1] = f2tf32(x1 - __uint_as_float(bh[1]));
#pragma unroll
                for (int tt = 0; tt < 2; tt++) {
                    mma_tf32(acc[tt][j], ah[tt], bh);
                    mma_tf32(acc[tt][j], ah[tt], bl);
                    if (prec == 3) mma_tf32(acc[tt][j], al[tt], bh);
                }
            }
        }
        __syncthreads();
        int nx = i + 3;
        if (nx < nsteps) STAGE(buf, nx);
        else cp_commit();
    }
#undef STAGE

    if (part) {
#pragma unroll
        for (int tt = 0; tt < 2; tt++)
#pragma unroll
            for (int j = 0; j < 8; j++) {
                int gr = m0 + tt * 16 + lr;
                int gc = nblk + n0 + j * 8 + 2 * lc;
                *(float2*)(part + (size_t)gr * N + gc) = make_float2(acc[tt][j][0], acc[tt][j][1]);
                *(float2*)(part + (size_t)(gr + 8) * N + gc) = make_float2(acc[tt][j][2], acc[tt][j][3]);
            }
    } else {
#pragma unroll
        for (int tt = 0; tt < 2; tt++)
#pragma unroll
            for (int j = 0; j < 8; j++) {
                int gr = m0 + tt * 16 + lr;
                int gc = nblk + n0 + j * 8 + 2 * lc;
                float b0 = bias ? bias[gc] : 0.f;
                float b1 = bias ? bias[gc + 1] : 0.f;
                *(float2*)(C + (size_t)gr * N + gc) = make_float2(acc[tt][j][0] + b0, acc[tt][j][1] + b1);
                *(float2*)(C + (size_t)(gr + 8) * N + gc) = make_float2(acc[tt][j][2] + b0, acc[tt][j][3] + b1);
            }
    }
}

__global__ __launch_bounds__(256, 2)
void gemm_tf32(const float* __restrict__ A, int K,
               const float* __restrict__ W,
               const float* __restrict__ bias,
               float* __restrict__ C, int N,
               float* __restrict__ Cpart, int prec)
{
    int ksplit = gridDim.y;
    int klen = K / ksplit;
    int kstart = blockIdx.y * klen;
    int nblk = blockIdx.x * 128;
    int t = threadIdx.x;
    int r0 = t >> 2;
    int k4 = (t & 3) * 4;
    float* part = (ksplit > 1) ? (Cpart + (size_t)blockIdx.y * 128 * N) : nullptr;
    gemm_body(A + (size_t)r0 * K + kstart + k4,
              A + (size_t)(r0 + 64) * K + kstart + k4,
              W + (size_t)(nblk + r0) * K + kstart + k4,
              W + (size_t)(nblk + r0 + 64) * K + kstart + k4,
              bias, C, N, part, nblk, klen / 16, prec);
}

// fused GRU GEMMs + embedding gather: grid (12, 8, 2)
__global__ __launch_bounds__(256, 2)
void gemm_gru(const float* __restrict__ hprev,
              const float* __restrict__ W_ih, const float* __restrict__ W_hh,
              const int* __restrict__ seq, const int* __restrict__ pos,
              const int* __restrict__ yr, const int* __restrict__ fr,
              const float* __restrict__ et, const float* __restrict__ ep,
              const float* __restrict__ ey, const float* __restrict__ ei)
{
    int N = 3 * Hq;
    int nblk = blockIdx.x * 128;
    int t = threadIdx.x;
    int r0 = t >> 2;
    int k4 = (t & 3) * 4;
    if (blockIdx.z == 0) {
        int K = 4 * Hq;
        int klen = K / 8;               // 256 -> one table per split
        int kstart = blockIdx.y * klen;
        int region = blockIdx.y >> 1;
        int coff = (blockIdx.y & 1) * 256 + k4;
        const float* tbl; const int* idxa;
        if (region == 0)      { tbl = et; idxa = seq; }
        else if (region == 1) { tbl = ep; idxa = pos; }
        else if (region == 2) { tbl = ey; idxa = yr; }
        else                  { tbl = ei; idxa = fr; }
        const float* a0 = tbl + (size_t)idxa[r0] * Hq + coff;
        const float* a1 = tbl + (size_t)idxa[r0 + 64] * Hq + coff;
        gemm_body(a0, a1,
                  W_ih + (size_t)(nblk + r0) * K + kstart + k4,
                  W_ih + (size_t)(nblk + r0 + 64) * K + kstart + k4,
                  nullptr, nullptr, N,
                  g_gemm_part + (size_t)blockIdx.y * 128 * N,
                  nblk, klen / 16, 3);
    } else {
        int K = Hq;
        int klen = K / 8;
        int kstart = blockIdx.y * klen;
        gemm_body(hprev + (size_t)r0 * K + kstart + k4,
                  hprev + (size_t)(r0 + 64) * K + kstart + k4,
                  W_hh + (size_t)(nblk + r0) * K + kstart + k4,
                  W_hh + (size_t)(nblk + r0 + 64) * K + kstart + k4,
                  nullptr, nullptr, N,
                  g_gemm_part2 + (size_t)blockIdx.y * 128 * N,
                  nblk, klen / 16, 3);
    }
}

__global__ void reduce_split(const float* __restrict__ part, const float* __restrict__ bias,
                             float* __restrict__ C, int total, int N, int ksplit, int act)
{
    int idx = blockIdx.x * 256 + threadIdx.x;
    if (idx >= total) return;
    float s = 0.f;
    for (int z = 0; z < ksplit; z++) s += part[(size_t)z * total + idx];
    s += bias[idx % N];
    if (act == 1) s = tanhf(s);
    C[idx] = s;
}

// ---------------- fused split-K reduce + GRU gates ----------------
__global__ void gate_fused_kernel(const float* __restrict__ hprev,
                                  const float* __restrict__ b_ih,
                                  const float* __restrict__ b_hh,
                                  float* __restrict__ out_h)
{
    int idx = blockIdx.x * 256 + threadIdx.x;
    int b = idx >> 9;
    int j = idx & 511;
    float xr = 0.f, xz = 0.f, xn = 0.f, hr = 0.f, hz = 0.f, hn = 0.f;
#pragma unroll
    for (int z = 0; z < 8; z++) {
        const float* P0 = g_gemm_part  + ((size_t)z * Bq + b) * (3 * Hq);
        const float* P1 = g_gemm_part2 + ((size_t)z * Bq + b) * (3 * Hq);
        xr += P0[j]; xz += P0[Hq + j]; xn += P0[2 * Hq + j];
        hr += P1[j]; hz += P1[Hq + j]; hn += P1[2 * Hq + j];
    }
    xr += b_ih[j]; xz += b_ih[Hq + j]; xn += b_ih[2 * Hq + j];
    hr += b_hh[j]; hz += b_hh[Hq + j]; hn += b_hh[2 * Hq + j];
    float r = 1.f / (1.f + __expf(-(xr + hr)));
    float z = 1.f / (1.f + __expf(-(xz + hz)));
    float n = tanhf(xn + r * hn);
    float hnew = (1.f - z) * n + z * hprev[idx];
    g_hnew[idx] = hnew;
    g_concat_in[(size_t)b * 2 * Hq + j] = hnew;
    if (out_h) out_h[idx] = hnew;
}

// ---------------- fused attention: single pass over enc ----------------
// grid (8, B), block 128: warp w owns chunk blockIdx.x*4+w -> 128 s values.
__global__ __launch_bounds__(128)
void attn_fused_kernel(const float* __restrict__ enc)
{
    int b = blockIdx.y;
    int t = threadIdx.x;
    int w = t >> 5;
    int lane = t & 31;
    int chunk = blockIdx.x * 4 + w;

    const float4* h4 = (const float4*)(g_hnew + (size_t)b * Hq);
    float4 h0 = h4[lane];
    float4 h1 = h4[lane + 32];
    float4 h2 = h4[lane + 64];
    float4 h3 = h4[lane + 96];

    float m = -1e30f, Z = 0.f;
    float4 c0 = make_float4(0.f,0.f,0.f,0.f), c1 = c0, c2 = c0, c3 = c0;

    int sbase = chunk * 128;
#pragma unroll 2
    for (int s0 = 0; s0 < 128; s0++) {
        int s = sbase + s0;
        const float4* e4 = (const float4*)(enc + ((size_t)s * Bq + b) * Hq);
        float4 e0 = e4[lane];
        float4 e1 = e4[lane + 32];
        float4 e2 = e4[lane + 64];
        float4 e3 = e4[lane + 96];
        float dp = e0.x*h0.x + e0.y*h0.y + e0.z*h0.z + e0.w*h0.w
                 + e1.x*h1.x + e1.y*h1.y + e1.z*h1.z + e1.w*h1.w
                 + e2.x*h2.x + e2.y*h2.y + e2.z*h2.z + e2.w*h2.w
                 + e3.x*h3.x + e3.y*h3.y + e3.z*h3.z + e3.w*h3.w;
#pragma unroll
        for (int off = 16; off > 0; off >>= 1)
            dp += __shfl_xor_sync(0xffffffffu, dp, off);
        if (lane == 0) g_scores[(size_t)b * Sq + s] = dp;
        if (dp <= m) {
            float p = __expf(dp - m);
            Z += p;
            c0.x += p*e0.x; c0.y += p*e0.y; c0.z += p*e0.z; c0.w += p*e0.w;
            c1.x += p*e1.x; c1.y += p*e1.y; c1.z += p*e1.z; c1.w += p*e1.w;
            c2.x += p*e2.x; c2.y += p*e2.y; c2.z += p*e2.z; c2.w += p*e2.w;
            c3.x += p*e3.x; c3.y += p*e3.y; c3.z += p*e3.z; c3.w += p*e3.w;
        } else {
            float corr = __expf(m - dp);
            Z = Z * corr + 1.f;
            c0.x = c0.x*corr + e0.x; c0.y = c0.y*corr + e0.y; c0.z = c0.z*corr + e0.z; c0.w = c0.w*corr + e0.w;
            c1.x = c1.x*corr + e1.x; c1.y = c1.y*corr + e1.y; c1.z = c1.z*corr + e1.z; c1.w = c1.w*corr + e1.w;
            c2.x = c2.x*corr + e2.x; c2.y = c2.y*corr + e2.y; c2.z = c2.z*corr + e2.z; c2.w = c2.w*corr + e2.w;
            c3.x = c3.x*corr + e3.x; c3.y = c3.y*corr + e3.y; c3.z = c3.z*corr + e3.z; c3.w = c3.w*corr + e3.w;
            m = dp;
        }
    }

    int pc = b * NCHUNK + chunk;
    float4* pctx = (float4*)(g_pctx + (size_t)pc * Hq);
    pctx[lane]      = c0;
    pctx[lane + 32] = c1;
    pctx[lane + 64] = c2;
    pctx[lane + 96] = c3;
    if (lane == 0) { g_pm[pc] = m; g_pz[pc] = Z; }
}

// ---------------- per-row stats: M, Zinv, per-chunk scale ----------------
// grid 16, block 256: warp per batch row (8 rows/block).
__global__ __launch_bounds__(256)
void attn_stats_kernel()
{
    int wid = threadIdx.x >> 5;
    int lane = threadIdx.x & 31;
    int b = blockIdx.x * 8 + wid;
    float m = g_pm[b * NCHUNK + lane];       // NCHUNK == 32
    float z = g_pz[b * NCHUNK + lane];
    float M = m;
#pragma unroll
    for (int off = 16; off > 0; off >>= 1)
        M = fmaxf(M, __shfl_xor_sync(0xffffffffu, M, off));
    float e = __expf(m - M);
    float zs = z * e;
#pragma unroll
    for (int off = 16; off > 0; off >>= 1)
        zs += __shfl_xor_sync(0xffffffffu, zs, off);
    float zinv = 1.f / zs;
    g_scale[b * NCHUNK + lane] = e * zinv;
    if (lane == 0) { g_M[b] = M; g_Zinv[b] = zinv; }
}

// ---------------- wide ctx reduce: one thread per (b,h) ----------------
__global__ __launch_bounds__(256)
void ctx_reduce_kernel()
{
    int idx = blockIdx.x * 256 + threadIdx.x;   // B*H
    int b = idx >> 9;
    int h = idx & 511;
    const float* sc = g_scale + b * NCHUNK;
    const float* p = g_pctx + (size_t)b * NCHUNK * Hq + h;
    float a = 0.f;
#pragma unroll 8
    for (int c = 0; c < NCHUNK; c++)
        a += p[(size_t)c * Hq] * sc[c];
    g_concat_in[(size_t)b * 2 * Hq + Hq + h] = a;
}

// ---------------- attn weights output ----------------
__global__ void attn_weights_kernel(float* __restrict__ out_attn)
{
    int idx = blockIdx.x * 256 + threadIdx.x;   // B*S
    int b = idx >> 12;
    out_attn[idx] = __expf(g_scores[idx] - g_M[b]) * g_Zinv[b];
}

// ---------------- launch ----------------
extern "C" void kernel_launch(void* const* d_in, const int* in_sizes, int n_in,
                              void* d_out, int out_size)
{
    const int* input_seq   = (const int*)d_in[0];
    const int* positions   = (const int*)d_in[1];
    const int* years       = (const int*)d_in[2];
    const int* froms       = (const int*)d_in[3];
    const float* last_h    = (const float*)d_in[4];
    const float* enc       = (const float*)d_in[5];
    const float* emb_tok   = (const float*)d_in[6];
    const float* emb_pos   = (const float*)d_in[7];
    const float* emb_year  = (const float*)d_in[8];
    const float* emb_inst  = (const float*)d_in[9];
    const float* W_ih      = (const float*)d_in[10];
    const float* b_ih      = (const float*)d_in[11];
    const float* W_hh      = (const float*)d_in[12];
    const float* b_hh      = (const float*)d_in[13];
    const float* W_concat  = (const float*)d_in[14];
    const float* b_concat  = (const float*)d_in[15];
    const float* W_out     = (const float*)d_in[16];
    const float* b_out     = (const float*)d_in[17];

    float* out = (float*)d_out;
    float* out_logits = out;
    float* out_h = nullptr;
    float* out_attn = nullptr;
    long long need = (long long)Bq * Vq + (long long)Bq * Hq + (long long)Bq * Sq;
    if ((long long)out_size >= need) {
        out_h = out + (size_t)Bq * Vq;
        out_attn = out_h + (size_t)Bq * Hq;
    }

    float *part, *concat_in, *concat_out;
    cudaGetSymbolAddress((void**)&part, g_gemm_part);
    cudaGetSymbolAddress((void**)&concat_in, g_concat_in);
    cudaGetSymbolAddress((void**)&concat_out, g_concat_out);

    cudaFuncSetAttribute(gemm_tf32, cudaFuncAttributeMaxDynamicSharedMemorySize, GEMM_SMEM_BYTES);
    cudaFuncSetAttribute(gemm_gru, cudaFuncAttributeMaxDynamicSharedMemorySize, GEMM_SMEM_BYTES);

    // 1. gx (embedding gather fused) AND gh in one launch (split-K 8, tf32x3)
    gemm_gru<<<dim3(12, 8, 2), 256, GEMM_SMEM_BYTES>>>(last_h, W_ih, W_hh,
        input_seq, positions, years, froms, emb_tok, emb_pos, emb_year, emb_inst);
    // 2. fused split-K reduce + gates -> h_new
    gate_fused_kernel<<<(Bq * Hq) / 256, 256>>>(last_h, b_ih, b_hh, out_h);
    // 3. fused scores + online-softmax context (single pass, one resident wave)
    attn_fused_kernel<<<dim3(8, Bq), 128>>>(enc);
    // 4. per-row stats (M, Zinv, chunk scales)
    attn_stats_kernel<<<16, 256>>>();
    // 5. wide ctx reduce -> concat_in[:, H:]
    ctx_reduce_kernel<<<(Bq * Hq) / 256, 256>>>();
    // 6. attn weights output
    if (out_attn)
        attn_weights_kernel<<<(Bq * Sq) / 256, 256>>>(out_attn);
    // 7. concat_out = tanh(concat_in @ W_concat^T + b_concat) (tf32x3, split-K 8)
    gemm_tf32<<<dim3(4, 8), 256, GEMM_SMEM_BYTES>>>(concat_in, 2 * Hq, W_concat, nullptr, nullptr, Hq, part, 3);
    reduce_split<<<(Bq * Hq + 255) / 256, 256>>>(part, b_concat, concat_out, Bq * Hq, Hq, 8, 1);
    // 8. logits = concat_out @ W_out^T + b_out  (tf32x2, split-K 1, direct out)
    gemm_tf32<<<dim3(Vq / 128, 1), 256, GEMM_SMEM_BYTES>>>(concat_out, Hq, W_out, b_out, out_logits, Vq, nullptr, 2);
}

// round 11
// speedup vs baseline: 1.1457x; 1.0837x over previous
#include <cuda_runtime.h>
#include <cuda_bf16.h>
#include <math.h>
#include <stdint.h>

#define Bq 128
#define Sq 4096
#define Hq 512
#define Vq 32000
#define NCHUNK 32           // 32 chunks of 128 s each

// ---------------- scratch (no allocations allowed) ----------------
__device__ float g_hnew[Bq * Hq];
__device__ float g_scores[Bq * Sq];
__device__ float g_pm[Bq * NCHUNK];
__device__ float g_pz[Bq * NCHUNK];
__device__ float g_pctx[Bq * NCHUNK * Hq];
__device__ float g_concat_in[Bq * 2 * Hq];
__device__ float g_concat_out[Bq * Hq];
__device__ float g_gemm_part [8 * Bq * 3 * Hq];
__device__ float g_gemm_part2[8 * Bq * 3 * Hq];

// ---------------- tf32 tensor-core GEMM, 3-deep cp.async ring ----------------
__device__ __forceinline__ uint32_t f2tf32(float x) {
    uint32_t r;
    asm("cvt.rna.tf32.f32 %0, %1;" : "=r"(r) : "f"(x));
    return r;
}
__device__ __forceinline__ void mma_tf32(float* d, const uint32_t* a, const uint32_t* b) {
    asm("mma.sync.aligned.m16n8k8.row.col.f32.tf32.tf32.f32 "
        "{%0,%1,%2,%3}, {%4,%5,%6,%7}, {%8,%9}, {%0,%1,%2,%3};"
        : "+f"(d[0]), "+f"(d[1]), "+f"(d[2]), "+f"(d[3])
        : "r"(a[0]), "r"(a[1]), "r"(a[2]), "r"(a[3]), "r"(b[0]), "r"(b[1]));
}
__device__ __forceinline__ void cp16(void* dst_smem, const void* src) {
    uint32_t d = (uint32_t)__cvta_generic_to_shared(dst_smem);
    asm volatile("cp.async.ca.shared.global [%0], [%1], 16;" :: "r"(d), "l"(src));
}
__device__ __forceinline__ void cp_commit() { asm volatile("cp.async.commit_group;"); }
template<int N> __device__ __forceinline__ void cp_wait() {
    asm volatile("cp.async.wait_group %0;" :: "n"(N));
}

#define LDA 20
#define TILE_F (128 * LDA)
#define GEMM_SMEM_BYTES (3 * 2 * TILE_F * 4)

// prec: 3 -> tf32x3 (fp32-grade), 2 -> x2 (~2e-4), 1 -> plain tf32 (~4e-4)
__device__ __forceinline__
void gemm_body(const float* aptr0, const float* aptr1,
               const float* wptr0, const float* wptr1,
               const float* __restrict__ bias,
               float* __restrict__ C, int N,
               float* __restrict__ part,
               int nblk, int nsteps, int prec)
{
    extern __shared__ float smx[];
    float* Asm = smx;
    float* Wsm = smx + 3 * TILE_F;

    int t = threadIdx.x;
    int wid = t >> 5, lane = t & 31;
    int lr = lane >> 2, lc = lane & 3;
    int m0 = (wid & 3) * 32;
    int n0 = (wid >> 2) * 64;
    int r0 = t >> 2;
    int k4 = (t & 3) * 4;

    float acc[2][8][4];
#pragma unroll
    for (int i = 0; i < 2; i++)
#pragma unroll
        for (int j = 0; j < 8; j++)
#pragma unroll
            for (int c = 0; c < 4; c++) acc[i][j][c] = 0.f;

#define STAGE(buf, step)                                              \
    do {                                                              \
        float* Ad = Asm + (buf) * TILE_F;                             \
        float* Wd = Wsm + (buf) * TILE_F;                             \
        cp16(Ad + r0 * LDA + k4,        aptr0 + (step) * 16);         \
        cp16(Ad + (r0 + 64) * LDA + k4, aptr1 + (step) * 16);         \
        cp16(Wd + r0 * LDA + k4,        wptr0 + (step) * 16);         \
        cp16(Wd + (r0 + 64) * LDA + k4, wptr1 + (step) * 16);         \
        cp_commit();                                                  \
    } while (0)

#pragma unroll
    for (int p = 0; p < 3; p++) {
        if (p < nsteps) STAGE(p, p);
        else cp_commit();
    }

    for (int i = 0; i < nsteps; i++) {
        cp_wait<2>();
        __syncthreads();
        int buf = i % 3;
        const float* Ab = Asm + buf * TILE_F;
        const float* Wb = Wsm + buf * TILE_F;
#pragma unroll
        for (int ks = 0; ks < 2; ks++) {
            int k0 = ks * 8;
            uint32_t ah[2][4], al[2][4];
#pragma unroll
            for (int tt = 0; tt < 2; tt++) {
                int rb = m0 + tt * 16;
#pragma unroll
                for (int q = 0; q < 4; q++) {
                    int rr = rb + lr + (q & 1) * 8;
                    int cc = k0 + lc + (q >> 1) * 4;
                    float x = Ab[rr * LDA + cc];
                    uint32_t hi = f2tf32(x);
                    ah[tt][q] = hi;
                    if (prec == 3) al[tt][q] = f2tf32(x - __uint_as_float(hi));
                }
            }
#pragma unroll
            for (int j = 0; j < 8; j++) {
                int rn = (n0 + j * 8 + lr) * LDA;
                float x0 = Wb[rn + k0 + lc];
                float x1 = Wb[rn + k0 + lc + 4];
                uint32_t bh[2], bl[2];
                bh[0] = f2tf32(x0);
                bh[1] = f2tf32(x1);
                if (prec >= 2) {
                    bl[0] = f2tf32(x0 - __uint_as_float(bh[0]));
                    bl[1] = f2tf32(x1 - __uint_as_float(bh[1]));
                }
#pragma unroll
                for (int tt = 0; tt < 2; tt++) {
                    mma_tf32(acc[tt][j], ah[tt], bh);
                    if (prec >= 2) mma_tf32(acc[tt][j], ah[tt], bl);
                    if (prec == 3) mma_tf32(acc[tt][j], al[tt], bh);
                }
            }
        }
        __syncthreads();
        int nx = i + 3;
        if (nx < nsteps) STAGE(buf, nx);
        else cp_commit();
    }
#undef STAGE

    if (part) {
#pragma unroll
        for (int tt = 0; tt < 2; tt++)
#pragma unroll
            for (int j = 0; j < 8; j++) {
                int gr = m0 + tt * 16 + lr;
                int gc = nblk + n0 + j * 8 + 2 * lc;
                *(float2*)(part + (size_t)gr * N + gc) = make_float2(acc[tt][j][0], acc[tt][j][1]);
                *(float2*)(part + (size_t)(gr + 8) * N + gc) = make_float2(acc[tt][j][2], acc[tt][j][3]);
            }
    } else {
#pragma unroll
        for (int tt = 0; tt < 2; tt++)
#pragma unroll
            for (int j = 0; j < 8; j++) {
                int gr = m0 + tt * 16 + lr;
                int gc = nblk + n0 + j * 8 + 2 * lc;
                float b0 = bias ? bias[gc] : 0.f;
                float b1 = bias ? bias[gc + 1] : 0.f;
                *(float2*)(C + (size_t)gr * N + gc) = make_float2(acc[tt][j][0] + b0, acc[tt][j][1] + b1);
                *(float2*)(C + (size_t)(gr + 8) * N + gc) = make_float2(acc[tt][j][2] + b0, acc[tt][j][3] + b1);
            }
    }
}

__global__ __launch_bounds__(256, 2)
void gemm_tf32(const float* __restrict__ A, int K,
               const float* __restrict__ W,
               const float* __restrict__ bias,
               float* __restrict__ C, int N,
               float* __restrict__ Cpart, int prec)
{
    int ksplit = gridDim.y;
    int klen = K / ksplit;
    int kstart = blockIdx.y * klen;
    int nblk = blockIdx.x * 128;
    int t = threadIdx.x;
    int r0 = t >> 2;
    int k4 = (t & 3) * 4;
    float* part = (ksplit > 1) ? (Cpart + (size_t)blockIdx.y * 128 * N) : nullptr;
    gemm_body(A + (size_t)r0 * K + kstart + k4,
              A + (size_t)(r0 + 64) * K + kstart + k4,
              W + (size_t)(nblk + r0) * K + kstart + k4,
              W + (size_t)(nblk + r0 + 64) * K + kstart + k4,
              bias, C, N, part, nblk, klen / 16, prec);
}

// fused GRU GEMMs + embedding gather: grid (12, 8, 2)
__global__ __launch_bounds__(256, 2)
void gemm_gru(const float* __restrict__ hprev,
              const float* __restrict__ W_ih, const float* __restrict__ W_hh,
              const int* __restrict__ seq, const int* __restrict__ pos,
              const int* __restrict__ yr, const int* __restrict__ fr,
              const float* __restrict__ et, const float* __restrict__ ep,
              const float* __restrict__ ey, const float* __restrict__ ei)
{
    int N = 3 * Hq;
    int nblk = blockIdx.x * 128;
    int t = threadIdx.x;
    int r0 = t >> 2;
    int k4 = (t & 3) * 4;
    if (blockIdx.z == 0) {
        int K = 4 * Hq;
        int klen = K / 8;               // 256 -> one table per split
        int kstart = blockIdx.y * klen;
        int region = blockIdx.y >> 1;
        int coff = (blockIdx.y & 1) * 256 + k4;
        const float* tbl; const int* idxa;
        if (region == 0)      { tbl = et; idxa = seq; }
        else if (region == 1) { tbl = ep; idxa = pos; }
        else if (region == 2) { tbl = ey; idxa = yr; }
        else                  { tbl = ei; idxa = fr; }
        const float* a0 = tbl + (size_t)idxa[r0] * Hq + coff;
        const float* a1 = tbl + (size_t)idxa[r0 + 64] * Hq + coff;
        gemm_body(a0, a1,
                  W_ih + (size_t)(nblk + r0) * K + kstart + k4,
                  W_ih + (size_t)(nblk + r0 + 64) * K + kstart + k4,
                  nullptr, nullptr, N,
                  g_gemm_part + (size_t)blockIdx.y * 128 * N,
                  nblk, klen / 16, 3);
    } else {
        int K = Hq;
        int klen = K / 8;
        int kstart = blockIdx.y * klen;
        gemm_body(hprev + (size_t)r0 * K + kstart + k4,
                  hprev + (size_t)(r0 + 64) * K + kstart + k4,
                  W_hh + (size_t)(nblk + r0) * K + kstart + k4,
                  W_hh + (size_t)(nblk + r0 + 64) * K + kstart + k4,
                  nullptr, nullptr, N,
                  g_gemm_part2 + (size_t)blockIdx.y * 128 * N,
                  nblk, klen / 16, 3);
    }
}

__global__ void reduce_split(const float* __restrict__ part, const float* __restrict__ bias,
                             float* __restrict__ C, int total, int N, int ksplit, int act)
{
    int idx = blockIdx.x * 256 + threadIdx.x;
    if (idx >= total) return;
    float s = 0.f;
    for (int z = 0; z < ksplit; z++) s += part[(size_t)z * total + idx];
    s += bias[idx % N];
    if (act == 1) s = tanhf(s);
    C[idx] = s;
}

// ---------------- fused split-K reduce + GRU gates ----------------
__global__ void gate_fused_kernel(const float* __restrict__ hprev,
                                  const float* __restrict__ b_ih,
                                  const float* __restrict__ b_hh,
                                  float* __restrict__ out_h)
{
    int idx = blockIdx.x * 256 + threadIdx.x;
    int b = idx >> 9;
    int j = idx & 511;
    float xr = 0.f, xz = 0.f, xn = 0.f, hr = 0.f, hz = 0.f, hn = 0.f;
#pragma unroll
    for (int z = 0; z < 8; z++) {
        const float* P0 = g_gemm_part  + ((size_t)z * Bq + b) * (3 * Hq);
        const float* P1 = g_gemm_part2 + ((size_t)z * Bq + b) * (3 * Hq);
        xr += P0[j]; xz += P0[Hq + j]; xn += P0[2 * Hq + j];
        hr += P1[j]; hz += P1[Hq + j]; hn += P1[2 * Hq + j];
    }
    xr += b_ih[j]; xz += b_ih[Hq + j]; xn += b_ih[2 * Hq + j];
    hr += b_hh[j]; hz += b_hh[Hq + j]; hn += b_hh[2 * Hq + j];
    float r = 1.f / (1.f + __expf(-(xr + hr)));
    float z = 1.f / (1.f + __expf(-(xz + hz)));
    float n = tanhf(xn + r * hn);
    float hnew = (1.f - z) * n + z * hprev[idx];
    g_hnew[idx] = hnew;
    g_concat_in[(size_t)b * 2 * Hq + j] = hnew;
    if (out_h) out_h[idx] = hnew;
}

// ---------------- fused attention: single pass over enc ----------------
__global__ __launch_bounds__(128)
void attn_fused_kernel(const float* __restrict__ enc)
{
    int b = blockIdx.y;
    int t = threadIdx.x;
    int w = t >> 5;
    int lane = t & 31;
    int chunk = blockIdx.x * 4 + w;

    const float4* h4 = (const float4*)(g_hnew + (size_t)b * Hq);
    float4 h0 = h4[lane];
    float4 h1 = h4[lane + 32];
    float4 h2 = h4[lane + 64];
    float4 h3 = h4[lane + 96];

    float m = -1e30f, Z = 0.f;
    float4 c0 = make_float4(0.f,0.f,0.f,0.f), c1 = c0, c2 = c0, c3 = c0;

    int sbase = chunk * 128;
#pragma unroll 2
    for (int s0 = 0; s0 < 128; s0++) {
        int s = sbase + s0;
        const float4* e4 = (const float4*)(enc + ((size_t)s * Bq + b) * Hq);
        float4 e0 = e4[lane];
        float4 e1 = e4[lane + 32];
        float4 e2 = e4[lane + 64];
        float4 e3 = e4[lane + 96];
        float dp = e0.x*h0.x + e0.y*h0.y + e0.z*h0.z + e0.w*h0.w
                 + e1.x*h1.x + e1.y*h1.y + e1.z*h1.z + e1.w*h1.w
                 + e2.x*h2.x + e2.y*h2.y + e2.z*h2.z + e2.w*h2.w
                 + e3.x*h3.x + e3.y*h3.y + e3.z*h3.z + e3.w*h3.w;
#pragma unroll
        for (int off = 16; off > 0; off >>= 1)
            dp += __shfl_xor_sync(0xffffffffu, dp, off);
        if (lane == 0) g_scores[(size_t)b * Sq + s] = dp;
        if (dp <= m) {
            float p = __expf(dp - m);
            Z += p;
            c0.x += p*e0.x; c0.y += p*e0.y; c0.z += p*e0.z; c0.w += p*e0.w;
            c1.x += p*e1.x; c1.y += p*e1.y; c1.z += p*e1.z; c1.w += p*e1.w;
            c2.x += p*e2.x; c2.y += p*e2.y; c2.z += p*e2.z; c2.w += p*e2.w;
            c3.x += p*e3.x; c3.y += p*e3.y; c3.z += p*e3.z; c3.w += p*e3.w;
        } else {
            float corr = __expf(m - dp);
            Z = Z * corr + 1.f;
            c0.x = c0.x*corr + e0.x; c0.y = c0.y*corr + e0.y; c0.z = c0.z*corr + e0.z; c0.w = c0.w*corr + e0.w;
            c1.x = c1.x*corr + e1.x; c1.y = c1.y*corr + e1.y; c1.z = c1.z*corr + e1.z; c1.w = c1.w*corr + e1.w;
            c2.x = c2.x*corr + e2.x; c2.y = c2.y*corr + e2.y; c2.z = c2.z*corr + e2.z; c2.w = c2.w*corr + e2.w;
            c3.x = c3.x*corr + e3.x; c3.y = c3.y*corr + e3.y; c3.z = c3.z*corr + e3.z; c3.w = c3.w*corr + e3.w;
            m = dp;
        }
    }

    int pc = b * NCHUNK + chunk;
    float4* pctx = (float4*)(g_pctx + (size_t)pc * Hq);
    pctx[lane]      = c0;
    pctx[lane + 32] = c1;
    pctx[lane + 64] = c2;
    pctx[lane + 96] = c3;
    if (lane == 0) { g_pm[pc] = m; g_pz[pc] = Z; }
}

// ---------------- merged attention epilogue ----------------
// grid (18, B), block 256. Every block inlines the cheap 32-chunk stats
// reduction, then: x<2 -> ctx reduce (h = x*256+t); x>=2 -> attn weights.
__global__ __launch_bounds__(256)
void attn_epilogue_kernel(float* __restrict__ out_attn)
{
    __shared__ float s_scale[NCHUNK];
    __shared__ float s_M, s_Zinv;
    int b = blockIdx.y;
    int part = blockIdx.x;
    int t = threadIdx.x;

    if (t < 32) {
        float m = g_pm[b * NCHUNK + t];
        float z = g_pz[b * NCHUNK + t];
        float M = m;
#pragma unroll
        for (int off = 16; off > 0; off >>= 1)
            M = fmaxf(M, __shfl_xor_sync(0xffffffffu, M, off));
        float e = __expf(m - M);
        float zs = z * e;
#pragma unroll
        for (int off = 16; off > 0; off >>= 1)
            zs += __shfl_xor_sync(0xffffffffu, zs, off);
        float zinv = 1.f / zs;
        s_scale[t] = e * zinv;
        if (t == 0) { s_M = M; s_Zinv = zinv; }
    }
    __syncthreads();

    if (part < 2) {
        int h = part * 256 + t;
        const float* p = g_pctx + (size_t)b * NCHUNK * Hq + h;
        float a = 0.f;
#pragma unroll 8
        for (int c = 0; c < NCHUNK; c++)
            a += p[(size_t)c * Hq] * s_scale[c];
        g_concat_in[(size_t)b * 2 * Hq + Hq + h] = a;
    } else if (out_attn) {
        int s = (part - 2) * 256 + t;
        out_attn[(size_t)b * Sq + s] =
            __expf(g_scores[(size_t)b * Sq + s] - s_M) * s_Zinv;
    }
}

// ---------------- launch ----------------
extern "C" void kernel_launch(void* const* d_in, const int* in_sizes, int n_in,
                              void* d_out, int out_size)
{
    const int* input_seq   = (const int*)d_in[0];
    const int* positions   = (const int*)d_in[1];
    const int* years       = (const int*)d_in[2];
    const int* froms       = (const int*)d_in[3];
    const float* last_h    = (const float*)d_in[4];
    const float* enc       = (const float*)d_in[5];
    const float* emb_tok   = (const float*)d_in[6];
    const float* emb_pos   = (const float*)d_in[7];
    const float* emb_year  = (const float*)d_in[8];
    const float* emb_inst  = (const float*)d_in[9];
    const float* W_ih      = (const float*)d_in[10];
    const float* b_ih      = (const float*)d_in[11];
    const float* W_hh      = (const float*)d_in[12];
    const float* b_hh      = (const float*)d_in[13];
    const float* W_concat  = (const float*)d_in[14];
    const float* b_concat  = (const float*)d_in[15];
    const float* W_out     = (const float*)d_in[16];
    const float* b_out     = (const float*)d_in[17];

    float* out = (float*)d_out;
    float* out_logits = out;
    float* out_h = nullptr;
    float* out_attn = nullptr;
    long long need = (long long)Bq * Vq + (long long)Bq * Hq + (long long)Bq * Sq;
    if ((long long)out_size >= need) {
        out_h = out + (size_t)Bq * Vq;
        out_attn = out_h + (size_t)Bq * Hq;
    }

    float *part, *concat_in, *concat_out;
    cudaGetSymbolAddress((void**)&part, g_gemm_part);
    cudaGetSymbolAddress((void**)&concat_in, g_concat_in);
    cudaGetSymbolAddress((void**)&concat_out, g_concat_out);

    cudaFuncSetAttribute(gemm_tf32, cudaFuncAttributeMaxDynamicSharedMemorySize, GEMM_SMEM_BYTES);
    cudaFuncSetAttribute(gemm_gru, cudaFuncAttributeMaxDynamicSharedMemorySize, GEMM_SMEM_BYTES);

    // 1. gx (embedding gather fused) AND gh in one launch (split-K 8, tf32x3)
    gemm_gru<<<dim3(12, 8, 2), 256, GEMM_SMEM_BYTES>>>(last_h, W_ih, W_hh,
        input_seq, positions, years, froms, emb_tok, emb_pos, emb_year, emb_inst);
    // 2. fused split-K reduce + gates -> h_new
    gate_fused_kernel<<<(Bq * Hq) / 256, 256>>>(last_h, b_ih, b_hh, out_h);
    // 3. fused scores + online-softmax context (single pass, one resident wave)
    attn_fused_kernel<<<dim3(8, Bq), 128>>>(enc);
    // 4. merged epilogue: stats inline + ctx reduce + attn weights
    attn_epilogue_kernel<<<dim3(18, Bq), 256>>>(out_attn);
    // 5. concat_out = tanh(concat_in @ W_concat^T + b_concat) (tf32x3, split-K 8)
    gemm_tf32<<<dim3(4, 8), 256, GEMM_SMEM_BYTES>>>(concat_in, 2 * Hq, W_concat, nullptr, nullptr, Hq, part, 3);
    reduce_split<<<(Bq * Hq + 255) / 256, 256>>>(part, b_concat, concat_out, Bq * Hq, Hq, 8, 1);
    // 6. logits = concat_out @ W_out^T + b_out  (plain tf32, split-K 1, direct out)
    gemm_tf32<<<dim3(Vq / 128, 1), 256, GEMM_SMEM_BYTES>>>(concat_out, Hq, W_out, b_out, out_logits, Vq, nullptr, 1);
}